// round 7
// baseline (speedup 1.0000x reference)
#include <cuda_runtime.h>
#include <cuda_bf16.h>
#include <cstdint>

// Problem constants (match reference)
#define N_NODES  100000
#define N_EDGES  1600000
#define IN_C     128
#define HID_C    128
#define OUT_C    64
#define N_GRAPHS 64

// ---------------- static device scratch (no allocations allowed) ----------------
// float4-typed so bases are 16B-aligned (RED.128 / STG.128 trap otherwise).
__device__ float4 g_h  [(size_t)N_NODES * 32];   // [N,128] GEMM output per layer
__device__ float4 g_acc[(size_t)N_NODES * 32];   // [N,128] edge-scatter accumulator
__device__ float4 g_x  [(size_t)N_NODES * 32];   // [N,128] layer output (next input)
__device__ float  g_dinv[N_NODES];
__device__ int    g_deg [N_NODES];
__device__ float4 g_pool[N_GRAPHS * 32];         // [G,128] pooled sums
__device__ float  g_cnt [N_GRAPHS];

// ---------------- init / degree / dinv ----------------
__global__ void init_misc_kernel() {
    int i = blockIdx.x * blockDim.x + threadIdx.x;
    if (i < N_NODES) g_deg[i] = 0;
    if (i < N_GRAPHS * 32) g_pool[i] = make_float4(0.f, 0.f, 0.f, 0.f);
    if (i < N_GRAPHS) g_cnt[i] = 0.f;
}

// edge_index is int32 on device (JAX x64 disabled: jnp.int64 -> int32).
__global__ void deg_kernel(const int* __restrict__ ei) {
    int stride = gridDim.x * blockDim.x;
    for (int e = blockIdx.x * blockDim.x + threadIdx.x; e < N_EDGES; e += stride) {
        int d = ei[N_EDGES + e];   // dst row
        atomicAdd(&g_deg[d], 1);
    }
}

__global__ void dinv_kernel() {
    int i = blockIdx.x * blockDim.x + threadIdx.x;
    if (i < N_NODES) {
        // +1 for the self-loop; deg >= 1 always
        g_dinv[i] = rsqrtf((float)(g_deg[i] + 1));
    }
}

__global__ void zero_acc_kernel() {
    const int total = N_NODES * 32;   // float4 count
    int i = blockIdx.x * blockDim.x + threadIdx.x;
    if (i < total) g_acc[i] = make_float4(0.f, 0.f, 0.f, 0.f);
}

// ---------------- GEMM: g_h = in[N,128] @ W[128,128] (fp32) ----------------
// Block: 256 threads, 64-row x 128-col tile, K staged in two 64-chunks.
// smem: W chunk 64x128 (32KB) + x chunk 64x64 (16KB) = 48KB static.
__global__ __launch_bounds__(256) void gemm_kernel(const float* __restrict__ in,
                                                   const float* __restrict__ W) {
    __shared__ float ws[64][128];
    __shared__ float xs[64][64];
    const int t  = threadIdx.x;
    const int tx = t & 31;    // column group: cols tx*4 .. tx*4+3
    const int ty = t >> 5;    // row group: rows ty*8 .. ty*8+7
    const int row0 = blockIdx.x * 64;

    float acc[8][4];
#pragma unroll
    for (int i = 0; i < 8; i++)
#pragma unroll
        for (int j = 0; j < 4; j++) acc[i][j] = 0.f;

    for (int k0 = 0; k0 < 128; k0 += 64) {
        // load W chunk: rows k0..k0+63, all 128 cols -> 2048 float4
        const float4* Wg = (const float4*)(W + (size_t)k0 * 128);
#pragma unroll
        for (int j = 0; j < 8; j++) {
            int idx = j * 256 + t;
            ((float4*)ws)[idx] = Wg[idx];
        }
        // load x chunk: 64 rows x 64 k -> 1024 float4 (tail rows zero-filled)
#pragma unroll
        for (int j = 0; j < 4; j++) {
            int idx = j * 256 + t;
            int r   = idx >> 4;
            int c4  = idx & 15;
            int row = row0 + r;
            float4 v = make_float4(0.f, 0.f, 0.f, 0.f);
            if (row < N_NODES) v = *(const float4*)(in + (size_t)row * 128 + k0 + c4 * 4);
            *(float4*)&xs[r][c4 * 4] = v;
        }
        __syncthreads();
#pragma unroll 8
        for (int kk = 0; kk < 64; kk++) {
            float4 w = *(const float4*)&ws[kk][tx * 4];
#pragma unroll
            for (int i = 0; i < 8; i++) {
                float xv = xs[ty * 8 + i][kk];
                acc[i][0] = fmaf(xv, w.x, acc[i][0]);
                acc[i][1] = fmaf(xv, w.y, acc[i][1]);
                acc[i][2] = fmaf(xv, w.z, acc[i][2]);
                acc[i][3] = fmaf(xv, w.w, acc[i][3]);
            }
        }
        __syncthreads();
    }
#pragma unroll
    for (int i = 0; i < 8; i++) {
        int row = row0 + ty * 8 + i;
        if (row < N_NODES)
            g_h[(size_t)row * 32 + tx] =
                make_float4(acc[i][0], acc[i][1], acc[i][2], acc[i][3]);
    }
}

// ---------------- edge scatter: acc[dst] += dinv[src]*dinv[dst] * h[src] ----------------
// One warp per edge; 32 lanes x float4 cover the 128 channels.
// Vector reduction (no return) keeps atomic count at 32 per edge.
__global__ void scatter_kernel(const int* __restrict__ ei) {
    const int lane  = threadIdx.x & 31;
    const int warp  = (blockIdx.x * blockDim.x + threadIdx.x) >> 5;
    const int nwarp = (gridDim.x * blockDim.x) >> 5;
    for (int e = warp; e < N_EDGES; e += nwarp) {
        int s = ei[e];
        int d = ei[N_EDGES + e];
        float nrm = g_dinv[s] * g_dinv[d];
        float4 v  = g_h[(size_t)s * 32 + lane];
        float4* op = &g_acc[(size_t)d * 32 + lane];
        asm volatile("red.global.add.v4.f32 [%0], {%1, %2, %3, %4};"
                     :: "l"(op), "f"(v.x * nrm), "f"(v.y * nrm),
                        "f"(v.z * nrm), "f"(v.w * nrm)
                     : "memory");
    }
}

// ---------------- epilogue: g_x = relu(acc + dinv^2 * h + b) ----------------
__global__ void epilogue_kernel(const float* __restrict__ b) {
    const int total = N_NODES * 32;   // float4 count
    int i = blockIdx.x * blockDim.x + threadIdx.x;
    if (i >= total) return;
    int c4   = i & 31;
    int node = i >> 5;
    float d2 = g_dinv[node];
    d2 = d2 * d2;
    float4 a  = g_acc[i];
    float4 h  = g_h[i];
    float4 bb = *(const float4*)(b + c4 * 4);
    float4 o;
    o.x = fmaxf(fmaf(d2, h.x, a.x) + bb.x, 0.f);
    o.y = fmaxf(fmaf(d2, h.y, a.y) + bb.y, 0.f);
    o.z = fmaxf(fmaf(d2, h.z, a.z) + bb.z, 0.f);
    o.w = fmaxf(fmaf(d2, h.w, a.w) + bb.w, 0.f);
    g_x[i] = o;
}

// ---------------- mean pool over graphs (batch is int32) ----------------
__global__ void pool_kernel(const int* __restrict__ batch) {
    const int lane  = threadIdx.x & 31;
    const int warp  = (blockIdx.x * blockDim.x + threadIdx.x) >> 5;
    const int nwarp = (gridDim.x * blockDim.x) >> 5;
    for (int n = warp; n < N_NODES; n += nwarp) {
        int g = batch[n];
        float4 v = g_x[(size_t)n * 32 + lane];
        float4* p = &g_pool[g * 32 + lane];
        asm volatile("red.global.add.v4.f32 [%0], {%1, %2, %3, %4};"
                     :: "l"(p), "f"(v.x), "f"(v.y), "f"(v.z), "f"(v.w)
                     : "memory");
        if (lane == 0) atomicAdd(&g_cnt[g], 1.0f);
    }
}

// ---------------- final: out[g,o] = (pool_sum[g] . Wlin[:,o]) / cnt[g] + blin[o] ----------------
__global__ void final_kernel(const float* __restrict__ Wlin,
                             const float* __restrict__ blin,
                             float* __restrict__ out) {
    __shared__ float ps[128];
    int g = blockIdx.x;
    int o = threadIdx.x;   // 64 threads
    for (int i = o; i < 128; i += 64) ps[i] = ((const float*)g_pool)[g * 128 + i];
    __syncthreads();
    float inv_cnt = 1.0f / fmaxf(g_cnt[g], 1.0f);
    float s = 0.f;
#pragma unroll 8
    for (int k = 0; k < 128; k++) s = fmaf(ps[k], Wlin[k * 64 + o], s);
    out[g * 64 + o] = s * inv_cnt + blin[o];
}

// ---------------- launcher ----------------
extern "C" void kernel_launch(void* const* d_in, const int* in_sizes, int n_in,
                              void* d_out, int out_size) {
    const float* x     = (const float*)d_in[0];
    const int*   ei    = (const int*)d_in[1];     // int32 (JAX x64 disabled)
    const int*   batch = (const int*)d_in[2];     // int32
    const float* W1    = (const float*)d_in[3];
    const float* b1    = (const float*)d_in[4];
    const float* W2    = (const float*)d_in[5];
    const float* b2    = (const float*)d_in[6];
    const float* W3    = (const float*)d_in[7];
    const float* b3    = (const float*)d_in[8];
    const float* Wlin  = (const float*)d_in[9];
    const float* blin  = (const float*)d_in[10];
    float* out = (float*)d_out;

    // Resolve the device address of g_x once (pure query; capture-safe, no alloc).
    static const float* gx_ptr = nullptr;
    if (!gx_ptr) {
        void* p = nullptr;
        cudaGetSymbolAddress(&p, g_x);
        gx_ptr = (const float*)p;
    }

    const int node_blocks = (N_NODES + 255) / 256;            // 391
    const int f4_blocks   = (N_NODES * 32 + 255) / 256;       // 12500
    const int gemm_blocks = (N_NODES + 63) / 64;              // 1563

    init_misc_kernel<<<node_blocks, 256>>>();
    deg_kernel<<<1024, 256>>>(ei);
    dinv_kernel<<<node_blocks, 256>>>();

    const float* Ws[3] = { W1, W2, W3 };
    const float* bs[3] = { b1, b2, b3 };

    for (int l = 0; l < 3; l++) {
        const float* in_ptr = (l == 0) ? x : gx_ptr;
        gemm_kernel<<<gemm_blocks, 256>>>(in_ptr, Ws[l]);
        zero_acc_kernel<<<f4_blocks, 256>>>();
        scatter_kernel<<<2048, 256>>>(ei);
        epilogue_kernel<<<f4_blocks, 256>>>(bs[l]);
    }

    pool_kernel<<<512, 256>>>(batch);
    final_kernel<<<N_GRAPHS, 64>>>(Wlin, blin, out);
}

// round 8
// speedup vs baseline: 1.2018x; 1.2018x over previous
#include <cuda_runtime.h>
#include <cuda_bf16.h>
#include <cstdint>

// Problem constants (match reference)
#define N_NODES  100000
#define N_EDGES  1600000
#define IN_C     128
#define HID_C    128
#define OUT_C    64
#define N_GRAPHS 64

// ---------------- static device scratch (no allocations allowed) ----------------
// float4-typed feature buffers: base 16B-aligned (STG.128 alignment).
__device__ float4 g_h  [(size_t)N_NODES * 32];   // [N,128] GEMM output per layer
__device__ float4 g_x  [(size_t)N_NODES * 32];   // [N,128] layer output (next input)
__device__ float  g_dinv[N_NODES];
__device__ int    g_deg [N_NODES];
__device__ int    g_off [N_NODES + 1];           // CSR row offsets (by dst)
__device__ int    g_cur [N_NODES];               // placement cursors
__device__ int2   g_edges[N_EDGES];              // {src, norm-bits} sorted by dst
__device__ float4 g_pool[N_GRAPHS * 32];         // [G,128] pooled sums
__device__ float  g_cnt [N_GRAPHS];

// ---------------- init / degree / dinv ----------------
__global__ void init_misc_kernel() {
    int i = blockIdx.x * blockDim.x + threadIdx.x;
    if (i < N_NODES) g_deg[i] = 0;
    if (i < N_GRAPHS * 32) g_pool[i] = make_float4(0.f, 0.f, 0.f, 0.f);
    if (i < N_GRAPHS) g_cnt[i] = 0.f;
}

// edge_index is int32 on device (JAX x64 disabled: jnp.int64 -> int32).
__global__ void deg_kernel(const int* __restrict__ ei) {
    int stride = gridDim.x * blockDim.x;
    for (int e = blockIdx.x * blockDim.x + threadIdx.x; e < N_EDGES; e += stride) {
        int d = ei[N_EDGES + e];   // dst row
        atomicAdd(&g_deg[d], 1);
    }
}

__global__ void dinv_kernel() {
    int i = blockIdx.x * blockDim.x + threadIdx.x;
    if (i < N_NODES) {
        // +1 for the self-loop; deg >= 1 always
        g_dinv[i] = rsqrtf((float)(g_deg[i] + 1));
    }
}

// ---------------- single-block exclusive scan of g_deg -> g_off, g_cur ----------------
// 1024 threads, each owns a contiguous chunk of ~98 nodes.
__global__ __launch_bounds__(1024) void scan_kernel() {
    __shared__ int part[1024];
    const int t = threadIdx.x;
    const int CH = (N_NODES + 1023) / 1024;   // 98
    const int beg = t * CH;
    const int end = min(beg + CH, N_NODES);

    int s = 0;
    for (int i = beg; i < end; i++) s += g_deg[i];
    part[t] = s;
    __syncthreads();

    // Hillis-Steele inclusive scan over 1024 partials
    for (int off = 1; off < 1024; off <<= 1) {
        int v = (t >= off) ? part[t - off] : 0;
        __syncthreads();
        part[t] += v;
        __syncthreads();
    }
    int base = (t == 0) ? 0 : part[t - 1];   // exclusive prefix for this chunk

    int run = base;
    for (int i = beg; i < end; i++) {
        g_off[i] = run;
        g_cur[i] = run;
        run += g_deg[i];
    }
    if (t == 1023) g_off[N_NODES] = N_EDGES;
}

// ---------------- CSR placement: edges bucketed by dst, norm precomputed ----------------
__global__ void place_kernel(const int* __restrict__ ei) {
    int stride = gridDim.x * blockDim.x;
    for (int e = blockIdx.x * blockDim.x + threadIdx.x; e < N_EDGES; e += stride) {
        int s = ei[e];
        int d = ei[N_EDGES + e];
        int pos = atomicAdd(&g_cur[d], 1);
        float nrm = g_dinv[s] * g_dinv[d];
        g_edges[pos] = make_int2(s, __float_as_int(nrm));
    }
}

// ---------------- GEMM: g_h = in[N,128] @ W[128,128] (fp32, at FFMA roof) ----------------
__global__ __launch_bounds__(256) void gemm_kernel(const float* __restrict__ in,
                                                   const float* __restrict__ W) {
    __shared__ float ws[64][128];
    __shared__ float xs[64][64];
    const int t  = threadIdx.x;
    const int tx = t & 31;    // column group: cols tx*4 .. tx*4+3
    const int ty = t >> 5;    // row group: rows ty*8 .. ty*8+7
    const int row0 = blockIdx.x * 64;

    float acc[8][4];
#pragma unroll
    for (int i = 0; i < 8; i++)
#pragma unroll
        for (int j = 0; j < 4; j++) acc[i][j] = 0.f;

    for (int k0 = 0; k0 < 128; k0 += 64) {
        const float4* Wg = (const float4*)(W + (size_t)k0 * 128);
#pragma unroll
        for (int j = 0; j < 8; j++) {
            int idx = j * 256 + t;
            ((float4*)ws)[idx] = Wg[idx];
        }
#pragma unroll
        for (int j = 0; j < 4; j++) {
            int idx = j * 256 + t;
            int r   = idx >> 4;
            int c4  = idx & 15;
            int row = row0 + r;
            float4 v = make_float4(0.f, 0.f, 0.f, 0.f);
            if (row < N_NODES) v = *(const float4*)(in + (size_t)row * 128 + k0 + c4 * 4);
            *(float4*)&xs[r][c4 * 4] = v;
        }
        __syncthreads();
#pragma unroll 8
        for (int kk = 0; kk < 64; kk++) {
            float4 w = *(const float4*)&ws[kk][tx * 4];
#pragma unroll
            for (int i = 0; i < 8; i++) {
                float xv = xs[ty * 8 + i][kk];
                acc[i][0] = fmaf(xv, w.x, acc[i][0]);
                acc[i][1] = fmaf(xv, w.y, acc[i][1]);
                acc[i][2] = fmaf(xv, w.z, acc[i][2]);
                acc[i][3] = fmaf(xv, w.w, acc[i][3]);
            }
        }
        __syncthreads();
    }
#pragma unroll
    for (int i = 0; i < 8; i++) {
        int row = row0 + ty * 8 + i;
        if (row < N_NODES)
            g_h[(size_t)row * 32 + tx] =
                make_float4(acc[i][0], acc[i][1], acc[i][2], acc[i][3]);
    }
}

// ---------------- fused gather + self-loop + bias + ReLU ----------------
// One warp per dst node; 32 lanes x float4 cover the 128 channels.
// acc = dinv^2*h[n] + sum_{(s->n)} nrm*h[s]; out = relu(acc + b)
__global__ __launch_bounds__(256) void gather_kernel(const float* __restrict__ b) {
    const int lane = threadIdx.x & 31;
    const int n    = (blockIdx.x * blockDim.x + threadIdx.x) >> 5;
    if (n >= N_NODES) return;

    const float4 bb = *(const float4*)(b + lane * 4);
    float d2 = g_dinv[n];
    d2 = d2 * d2;

    float4 h0 = g_h[(size_t)n * 32 + lane];
    float4 acc = make_float4(d2 * h0.x, d2 * h0.y, d2 * h0.z, d2 * h0.w);

    const int beg = g_off[n];
    const int end = g_off[n + 1];

    int e = beg;
    // unroll-2 for memory-level parallelism on the random h gathers
    for (; e + 1 < end; e += 2) {
        int2 e0 = g_edges[e];
        int2 e1 = g_edges[e + 1];
        float4 v0 = g_h[(size_t)e0.x * 32 + lane];
        float4 v1 = g_h[(size_t)e1.x * 32 + lane];
        float n0 = __int_as_float(e0.y);
        float n1 = __int_as_float(e1.y);
        acc.x = fmaf(n0, v0.x, acc.x); acc.y = fmaf(n0, v0.y, acc.y);
        acc.z = fmaf(n0, v0.z, acc.z); acc.w = fmaf(n0, v0.w, acc.w);
        acc.x = fmaf(n1, v1.x, acc.x); acc.y = fmaf(n1, v1.y, acc.y);
        acc.z = fmaf(n1, v1.z, acc.z); acc.w = fmaf(n1, v1.w, acc.w);
    }
    if (e < end) {
        int2 e0 = g_edges[e];
        float4 v0 = g_h[(size_t)e0.x * 32 + lane];
        float n0 = __int_as_float(e0.y);
        acc.x = fmaf(n0, v0.x, acc.x); acc.y = fmaf(n0, v0.y, acc.y);
        acc.z = fmaf(n0, v0.z, acc.z); acc.w = fmaf(n0, v0.w, acc.w);
    }

    float4 o;
    o.x = fmaxf(acc.x + bb.x, 0.f);
    o.y = fmaxf(acc.y + bb.y, 0.f);
    o.z = fmaxf(acc.z + bb.z, 0.f);
    o.w = fmaxf(acc.w + bb.w, 0.f);
    g_x[(size_t)n * 32 + lane] = o;
}

// ---------------- mean pool over graphs (batch is int32) ----------------
__global__ void pool_kernel(const int* __restrict__ batch) {
    const int lane  = threadIdx.x & 31;
    const int warp  = (blockIdx.x * blockDim.x + threadIdx.x) >> 5;
    const int nwarp = (gridDim.x * blockDim.x) >> 5;
    for (int n = warp; n < N_NODES; n += nwarp) {
        int g = batch[n];
        float4 v = g_x[(size_t)n * 32 + lane];
        float4* p = &g_pool[g * 32 + lane];
        asm volatile("red.global.add.v4.f32 [%0], {%1, %2, %3, %4};"
                     :: "l"(p), "f"(v.x), "f"(v.y), "f"(v.z), "f"(v.w)
                     : "memory");
        if (lane == 0) atomicAdd(&g_cnt[g], 1.0f);
    }
}

// ---------------- final: out[g,o] = (pool_sum[g] . Wlin[:,o]) / cnt[g] + blin[o] ----------------
__global__ void final_kernel(const float* __restrict__ Wlin,
                             const float* __restrict__ blin,
                             float* __restrict__ out) {
    __shared__ float ps[128];
    int g = blockIdx.x;
    int o = threadIdx.x;   // 64 threads
    for (int i = o; i < 128; i += 64) ps[i] = ((const float*)g_pool)[g * 128 + i];
    __syncthreads();
    float inv_cnt = 1.0f / fmaxf(g_cnt[g], 1.0f);
    float s = 0.f;
#pragma unroll 8
    for (int k = 0; k < 128; k++) s = fmaf(ps[k], Wlin[k * 64 + o], s);
    out[g * 64 + o] = s * inv_cnt + blin[o];
}

// ---------------- launcher ----------------
extern "C" void kernel_launch(void* const* d_in, const int* in_sizes, int n_in,
                              void* d_out, int out_size) {
    const float* x     = (const float*)d_in[0];
    const int*   ei    = (const int*)d_in[1];     // int32 (JAX x64 disabled)
    const int*   batch = (const int*)d_in[2];     // int32
    const float* W1    = (const float*)d_in[3];
    const float* b1    = (const float*)d_in[4];
    const float* W2    = (const float*)d_in[5];
    const float* b2    = (const float*)d_in[6];
    const float* W3    = (const float*)d_in[7];
    const float* b3    = (const float*)d_in[8];
    const float* Wlin  = (const float*)d_in[9];
    const float* blin  = (const float*)d_in[10];
    float* out = (float*)d_out;

    // Resolve the device address of g_x once (pure query; capture-safe, no alloc).
    static const float* gx_ptr = nullptr;
    if (!gx_ptr) {
        void* p = nullptr;
        cudaGetSymbolAddress(&p, g_x);
        gx_ptr = (const float*)p;
    }

    const int node_blocks   = (N_NODES + 255) / 256;          // 391
    const int gemm_blocks   = (N_NODES + 63) / 64;            // 1563
    const int gather_blocks = (N_NODES * 32 + 255) / 256;     // 12500 (1 warp/node)

    init_misc_kernel<<<node_blocks, 256>>>();
    deg_kernel<<<1024, 256>>>(ei);
    dinv_kernel<<<node_blocks, 256>>>();
    scan_kernel<<<1, 1024>>>();
    place_kernel<<<1024, 256>>>(ei);

    const float* Ws[3] = { W1, W2, W3 };
    const float* bs[3] = { b1, b2, b3 };

    for (int l = 0; l < 3; l++) {
        const float* in_ptr = (l == 0) ? x : gx_ptr;
        gemm_kernel<<<gemm_blocks, 256>>>(in_ptr, Ws[l]);
        gather_kernel<<<gather_blocks, 256>>>(bs[l]);
    }

    pool_kernel<<<512, 256>>>(batch);
    final_kernel<<<N_GRAPHS, 64>>>(Wlin, blin, out);
}

// round 10
// speedup vs baseline: 1.5107x; 1.2571x over previous
#include <cuda_runtime.h>
#include <cuda_bf16.h>
#include <cstdint>

// Problem constants (match reference)
#define N_NODES  100000
#define N_EDGES  1600000
#define IN_C     128
#define HID_C    128
#define OUT_C    64
#define N_GRAPHS 64

#define SCAN_CH   256                              // nodes per scan block
#define SCAN_NB   ((N_NODES + SCAN_CH - 1) / SCAN_CH)   // 391

// ---------------- static device scratch (no allocations allowed) ----------------
// float4-typed feature buffers: base 16B-aligned (STG.128 alignment).
__device__ float4 g_h  [(size_t)N_NODES * 32];   // [N,128] GEMM output per layer
__device__ float4 g_x  [(size_t)N_NODES * 32];   // [N,128] layer output (next input)
__device__ float  g_dinv[N_NODES];
__device__ int    g_deg [N_NODES];
__device__ int    g_off [N_NODES + 1];           // CSR row offsets (by dst)
__device__ int    g_cur [N_NODES];               // placement cursors
__device__ int2   g_edges[N_EDGES];              // {src, norm-bits} sorted by dst
__device__ int    g_part [SCAN_NB];              // per-block degree sums
__device__ int    g_partpre[SCAN_NB];            // exclusive prefix of partials
__device__ float4 g_pool[N_GRAPHS * 32];         // [G,128] pooled sums
__device__ float  g_cnt [N_GRAPHS];

// ---------------- init / degree ----------------
__global__ void init_misc_kernel() {
    int i = blockIdx.x * blockDim.x + threadIdx.x;
    if (i < N_NODES) g_deg[i] = 0;
    if (i < N_GRAPHS * 32) g_pool[i] = make_float4(0.f, 0.f, 0.f, 0.f);
    if (i < N_GRAPHS) g_cnt[i] = 0.f;
}

// edge_index is int32 on device (JAX x64 disabled: jnp.int64 -> int32).
__global__ void deg_kernel(const int* __restrict__ ei) {
    int stride = gridDim.x * blockDim.x;
    for (int e = blockIdx.x * blockDim.x + threadIdx.x; e < N_EDGES; e += stride) {
        int d = ei[N_EDGES + e];   // dst row
        atomicAdd(&g_deg[d], 1);
    }
}

// ---------------- 3-phase grid-wide exclusive scan of g_deg ----------------
// Phase 1: per-block degree sums (391 blocks x 256 threads)
__global__ __launch_bounds__(SCAN_CH) void part_kernel() {
    __shared__ int sh[SCAN_CH];
    int i = blockIdx.x * SCAN_CH + threadIdx.x;
    int v = (i < N_NODES) ? g_deg[i] : 0;
    sh[threadIdx.x] = v;
    __syncthreads();
    for (int off = SCAN_CH / 2; off > 0; off >>= 1) {
        if (threadIdx.x < off) sh[threadIdx.x] += sh[threadIdx.x + off];
        __syncthreads();
    }
    if (threadIdx.x == 0) g_part[blockIdx.x] = sh[0];
}

// Phase 2: scan the 391 partials in one small block (smem-resident)
__global__ __launch_bounds__(512) void scan_part_kernel() {
    __shared__ int sh[512];
    int t = threadIdx.x;
    sh[t] = (t < SCAN_NB) ? g_part[t] : 0;
    __syncthreads();
    for (int off = 1; off < 512; off <<= 1) {
        int v = (t >= off) ? sh[t - off] : 0;
        __syncthreads();
        sh[t] += v;
        __syncthreads();
    }
    if (t < SCAN_NB) g_partpre[t] = (t == 0) ? 0 : sh[t - 1];
}

// Phase 3: block-level exclusive scan + base -> g_off/g_cur; fuse dinv.
__global__ __launch_bounds__(SCAN_CH) void offsets_kernel() {
    __shared__ int sh[SCAN_CH];
    int t = threadIdx.x;
    int i = blockIdx.x * SCAN_CH + t;
    int d = (i < N_NODES) ? g_deg[i] : 0;
    sh[t] = d;
    __syncthreads();
    // Hillis-Steele inclusive scan over 256 values
    for (int off = 1; off < SCAN_CH; off <<= 1) {
        int v = (t >= off) ? sh[t - off] : 0;
        __syncthreads();
        sh[t] += v;
        __syncthreads();
    }
    if (i < N_NODES) {
        int base = g_partpre[blockIdx.x];
        int off  = base + sh[t] - d;          // exclusive
        g_off[i] = off;
        g_cur[i] = off;
        // fused dinv: +1 for the self-loop
        g_dinv[i] = rsqrtf((float)(d + 1));
        if (i == N_NODES - 1) g_off[N_NODES] = N_EDGES;
    }
}

// ---------------- CSR placement: edges bucketed by dst, norm precomputed ----------------
__global__ void place_kernel(const int* __restrict__ ei) {
    int stride = gridDim.x * blockDim.x;
    for (int e = blockIdx.x * blockDim.x + threadIdx.x; e < N_EDGES; e += stride) {
        int s = ei[e];
        int d = ei[N_EDGES + e];
        int pos = atomicAdd(&g_cur[d], 1);
        float nrm = g_dinv[s] * g_dinv[d];
        g_edges[pos] = make_int2(s, __float_as_int(nrm));
    }
}

// ---------------- GEMM: g_h = in[N,128] @ W[128,128] (fp32, at FFMA roof) ----------------
__global__ __launch_bounds__(256) void gemm_kernel(const float* __restrict__ in,
                                                   const float* __restrict__ W) {
    __shared__ float ws[64][128];
    __shared__ float xs[64][64];
    const int t  = threadIdx.x;
    const int tx = t & 31;    // column group: cols tx*4 .. tx*4+3
    const int ty = t >> 5;    // row group: rows ty*8 .. ty*8+7
    const int row0 = blockIdx.x * 64;

    float acc[8][4];
#pragma unroll
    for (int i = 0; i < 8; i++)
#pragma unroll
        for (int j = 0; j < 4; j++) acc[i][j] = 0.f;

    for (int k0 = 0; k0 < 128; k0 += 64) {
        const float4* Wg = (const float4*)(W + (size_t)k0 * 128);
#pragma unroll
        for (int j = 0; j < 8; j++) {
            int idx = j * 256 + t;
            ((float4*)ws)[idx] = Wg[idx];
        }
#pragma unroll
        for (int j = 0; j < 4; j++) {
            int idx = j * 256 + t;
            int r   = idx >> 4;
            int c4  = idx & 15;
            int row = row0 + r;
            float4 v = make_float4(0.f, 0.f, 0.f, 0.f);
            if (row < N_NODES) v = *(const float4*)(in + (size_t)row * 128 + k0 + c4 * 4);
            *(float4*)&xs[r][c4 * 4] = v;
        }
        __syncthreads();
#pragma unroll 8
        for (int kk = 0; kk < 64; kk++) {
            float4 w = *(const float4*)&ws[kk][tx * 4];
#pragma unroll
            for (int i = 0; i < 8; i++) {
                float xv = xs[ty * 8 + i][kk];
                acc[i][0] = fmaf(xv, w.x, acc[i][0]);
                acc[i][1] = fmaf(xv, w.y, acc[i][1]);
                acc[i][2] = fmaf(xv, w.z, acc[i][2]);
                acc[i][3] = fmaf(xv, w.w, acc[i][3]);
            }
        }
        __syncthreads();
    }
#pragma unroll
    for (int i = 0; i < 8; i++) {
        int row = row0 + ty * 8 + i;
        if (row < N_NODES)
            g_h[(size_t)row * 32 + tx] =
                make_float4(acc[i][0], acc[i][1], acc[i][2], acc[i][3]);
    }
}

// ---------------- fused gather + self-loop + bias + ReLU ----------------
// One warp per dst node; 32 lanes x float4 cover the 128 channels.
// acc = dinv^2*h[n] + sum_{(s->n)} nrm*h[s]; out = relu(acc + b)
__global__ __launch_bounds__(256) void gather_kernel(const float* __restrict__ b) {
    const int lane = threadIdx.x & 31;
    const int n    = (blockIdx.x * blockDim.x + threadIdx.x) >> 5;
    if (n >= N_NODES) return;

    const float4 bb = *(const float4*)(b + lane * 4);
    float d2 = g_dinv[n];
    d2 = d2 * d2;

    float4 h0 = g_h[(size_t)n * 32 + lane];
    float4 acc = make_float4(d2 * h0.x, d2 * h0.y, d2 * h0.z, d2 * h0.w);

    const int beg = g_off[n];
    const int end = g_off[n + 1];

    int e = beg;
    // unroll-2 for memory-level parallelism on the random h gathers
    for (; e + 1 < end; e += 2) {
        int2 e0 = g_edges[e];
        int2 e1 = g_edges[e + 1];
        float4 v0 = g_h[(size_t)e0.x * 32 + lane];
        float4 v1 = g_h[(size_t)e1.x * 32 + lane];
        float n0 = __int_as_float(e0.y);
        float n1 = __int_as_float(e1.y);
        acc.x = fmaf(n0, v0.x, acc.x); acc.y = fmaf(n0, v0.y, acc.y);
        acc.z = fmaf(n0, v0.z, acc.z); acc.w = fmaf(n0, v0.w, acc.w);
        acc.x = fmaf(n1, v1.x, acc.x); acc.y = fmaf(n1, v1.y, acc.y);
        acc.z = fmaf(n1, v1.z, acc.z); acc.w = fmaf(n1, v1.w, acc.w);
    }
    if (e < end) {
        int2 e0 = g_edges[e];
        float4 v0 = g_h[(size_t)e0.x * 32 + lane];
        float n0 = __int_as_float(e0.y);
        acc.x = fmaf(n0, v0.x, acc.x); acc.y = fmaf(n0, v0.y, acc.y);
        acc.z = fmaf(n0, v0.z, acc.z); acc.w = fmaf(n0, v0.w, acc.w);
    }

    float4 o;
    o.x = fmaxf(acc.x + bb.x, 0.f);
    o.y = fmaxf(acc.y + bb.y, 0.f);
    o.z = fmaxf(acc.z + bb.z, 0.f);
    o.w = fmaxf(acc.w + bb.w, 0.f);
    g_x[(size_t)n * 32 + lane] = o;
}

// ---------------- mean pool over graphs (batch is int32) ----------------
__global__ void pool_kernel(const int* __restrict__ batch) {
    const int lane  = threadIdx.x & 31;
    const int warp  = (blockIdx.x * blockDim.x + threadIdx.x) >> 5;
    const int nwarp = (gridDim.x * blockDim.x) >> 5;
    for (int n = warp; n < N_NODES; n += nwarp) {
        int g = batch[n];
        float4 v = g_x[(size_t)n * 32 + lane];
        float4* p = &g_pool[g * 32 + lane];
        asm volatile("red.global.add.v4.f32 [%0], {%1, %2, %3, %4};"
                     :: "l"(p), "f"(v.x), "f"(v.y), "f"(v.z), "f"(v.w)
                     : "memory");
        if (lane == 0) atomicAdd(&g_cnt[g], 1.0f);
    }
}

// ---------------- final: out[g,o] = (pool_sum[g] . Wlin[:,o]) / cnt[g] + blin[o] ----------------
__global__ void final_kernel(const float* __restrict__ Wlin,
                             const float* __restrict__ blin,
                             float* __restrict__ out) {
    __shared__ float ps[128];
    int g = blockIdx.x;
    int o = threadIdx.x;   // 64 threads
    for (int i = o; i < 128; i += 64) ps[i] = ((const float*)g_pool)[g * 128 + i];
    __syncthreads();
    float inv_cnt = 1.0f / fmaxf(g_cnt[g], 1.0f);
    float s = 0.f;
#pragma unroll 8
    for (int k = 0; k < 128; k++) s = fmaf(ps[k], Wlin[k * 64 + o], s);
    out[g * 64 + o] = s * inv_cnt + blin[o];
}

// ---------------- launcher ----------------
extern "C" void kernel_launch(void* const* d_in, const int* in_sizes, int n_in,
                              void* d_out, int out_size) {
    const float* x     = (const float*)d_in[0];
    const int*   ei    = (const int*)d_in[1];     // int32 (JAX x64 disabled)
    const int*   batch = (const int*)d_in[2];     // int32
    const float* W1    = (const float*)d_in[3];
    const float* b1    = (const float*)d_in[4];
    const float* W2    = (const float*)d_in[5];
    const float* b2    = (const float*)d_in[6];
    const float* W3    = (const float*)d_in[7];
    const float* b3    = (const float*)d_in[8];
    const float* Wlin  = (const float*)d_in[9];
    const float* blin  = (const float*)d_in[10];
    float* out = (float*)d_out;

    // Resolve the device address of g_x once (pure query; capture-safe, no alloc).
    static const float* gx_ptr = nullptr;
    if (!gx_ptr) {
        void* p = nullptr;
        cudaGetSymbolAddress(&p, g_x);
        gx_ptr = (const float*)p;
    }

    const int node_blocks   = (N_NODES + 255) / 256;          // 391
    const int gemm_blocks   = (N_NODES + 63) / 64;            // 1563
    const int gather_blocks = (N_NODES * 32 + 255) / 256;     // 12500 (1 warp/node)

    init_misc_kernel<<<node_blocks, 256>>>();
    deg_kernel<<<1024, 256>>>(ei);
    part_kernel<<<SCAN_NB, SCAN_CH>>>();
    scan_part_kernel<<<1, 512>>>();
    offsets_kernel<<<SCAN_NB, SCAN_CH>>>();
    place_kernel<<<1024, 256>>>(ei);

    const float* Ws[3] = { W1, W2, W3 };
    const float* bs[3] = { b1, b2, b3 };

    for (int l = 0; l < 3; l++) {
        const float* in_ptr = (l == 0) ? x : gx_ptr;
        gemm_kernel<<<gemm_blocks, 256>>>(in_ptr, Ws[l]);
        gather_kernel<<<gather_blocks, 256>>>(bs[l]);
    }

    pool_kernel<<<512, 256>>>(batch);
    final_kernel<<<N_GRAPHS, 64>>>(Wlin, blin, out);
}

// round 13
// speedup vs baseline: 1.6581x; 1.0976x over previous
#include <cuda_runtime.h>
#include <cuda_bf16.h>
#include <cstdint>

// Problem constants (match reference)
#define N_NODES  100000
#define N_EDGES  1600000
#define N_GRAPHS 64

#define SCAN_CH   256
#define SCAN_NB   ((N_NODES + SCAN_CH - 1) / SCAN_CH)   // 391

// ---------------- static device scratch (no allocations allowed) ----------------
// 16B/8B-aligned types so wide stores never trap.
__device__ uint2  g_hb [(size_t)N_NODES * 32];   // [N,128] bf16 GEMM output (4 ch / uint2)
__device__ float4 g_x  [(size_t)N_NODES * 32];   // [N,128] fp32 layer output (next input)
__device__ float  g_dinv[N_NODES];
__device__ int    g_deg [N_NODES];
__device__ int    g_off [N_NODES + 1];           // CSR row offsets (by dst)
__device__ int    g_cur [N_NODES];               // placement cursors
__device__ int2   g_edges[N_EDGES];              // {src, norm-bits} sorted by dst
__device__ int    g_part [SCAN_NB];
__device__ int    g_partpre[SCAN_NB];
__device__ float4 g_pool[N_GRAPHS * 32];
__device__ float  g_cnt [N_GRAPHS];

// ---------------- init / degree ----------------
__global__ void init_misc_kernel() {
    int i = blockIdx.x * blockDim.x + threadIdx.x;
    if (i < N_NODES) g_deg[i] = 0;
    if (i < N_GRAPHS * 32) g_pool[i] = make_float4(0.f, 0.f, 0.f, 0.f);
    if (i < N_GRAPHS) g_cnt[i] = 0.f;
}

// edge_index is int32 on device (JAX x64 disabled: jnp.int64 -> int32).
__global__ void deg_kernel(const int* __restrict__ ei) {
    int stride = gridDim.x * blockDim.x;
    for (int e = blockIdx.x * blockDim.x + threadIdx.x; e < N_EDGES; e += stride) {
        atomicAdd(&g_deg[ei[N_EDGES + e]], 1);
    }
}

// ---------------- 3-phase grid-wide exclusive scan of g_deg ----------------
__global__ __launch_bounds__(SCAN_CH) void part_kernel() {
    __shared__ int sh[SCAN_CH];
    int i = blockIdx.x * SCAN_CH + threadIdx.x;
    sh[threadIdx.x] = (i < N_NODES) ? g_deg[i] : 0;
    __syncthreads();
    for (int off = SCAN_CH / 2; off > 0; off >>= 1) {
        if (threadIdx.x < off) sh[threadIdx.x] += sh[threadIdx.x + off];
        __syncthreads();
    }
    if (threadIdx.x == 0) g_part[blockIdx.x] = sh[0];
}

__global__ __launch_bounds__(512) void scan_part_kernel() {
    __shared__ int sh[512];
    int t = threadIdx.x;
    sh[t] = (t < SCAN_NB) ? g_part[t] : 0;
    __syncthreads();
    for (int off = 1; off < 512; off <<= 1) {
        int v = (t >= off) ? sh[t - off] : 0;
        __syncthreads();
        sh[t] += v;
        __syncthreads();
    }
    if (t < SCAN_NB) g_partpre[t] = (t == 0) ? 0 : sh[t - 1];
}

__global__ __launch_bounds__(SCAN_CH) void offsets_kernel() {
    __shared__ int sh[SCAN_CH];
    int t = threadIdx.x;
    int i = blockIdx.x * SCAN_CH + t;
    int d = (i < N_NODES) ? g_deg[i] : 0;
    sh[t] = d;
    __syncthreads();
    for (int off = 1; off < SCAN_CH; off <<= 1) {
        int v = (t >= off) ? sh[t - off] : 0;
        __syncthreads();
        sh[t] += v;
        __syncthreads();
    }
    if (i < N_NODES) {
        int off = g_partpre[blockIdx.x] + sh[t] - d;   // exclusive
        g_off[i] = off;
        g_cur[i] = off;
        g_dinv[i] = rsqrtf((float)(d + 1));            // +1 self-loop
        if (i == N_NODES - 1) g_off[N_NODES] = N_EDGES;
    }
}

// ---------------- CSR placement: edges bucketed by dst, norm precomputed ----------------
__global__ void place_kernel(const int* __restrict__ ei) {
    int stride = gridDim.x * blockDim.x;
    for (int e = blockIdx.x * blockDim.x + threadIdx.x; e < N_EDGES; e += stride) {
        int s = ei[e];
        int d = ei[N_EDGES + e];
        int pos = atomicAdd(&g_cur[d], 1);
        float nrm = g_dinv[s] * g_dinv[d];
        g_edges[pos] = make_int2(s, __float_as_int(nrm));
    }
}

// ---------------- GEMM: g_hb = bf16(in[N,128] @ W[128,128]) (fp32 accumulate) ----------------
// Block: 256 threads, 64-row x 128-col tile, K staged in two 64-chunks.
__global__ __launch_bounds__(256) void gemm_kernel(const float* __restrict__ in,
                                                   const float* __restrict__ W) {
    __shared__ float ws[64][128];
    __shared__ float xs[64][64];
    const int t  = threadIdx.x;
    const int tx = t & 31;    // column group: cols tx*4 .. tx*4+3
    const int ty = t >> 5;    // row group: rows ty*8 .. ty*8+7
    const int row0 = blockIdx.x * 64;

    float acc[8][4];
#pragma unroll
    for (int i = 0; i < 8; i++)
#pragma unroll
        for (int j = 0; j < 4; j++) acc[i][j] = 0.f;

    for (int k0 = 0; k0 < 128; k0 += 64) {
        const float4* Wg = (const float4*)(W + (size_t)k0 * 128);
#pragma unroll
        for (int j = 0; j < 8; j++) {
            int idx = j * 256 + t;
            ((float4*)ws)[idx] = Wg[idx];
        }
#pragma unroll
        for (int j = 0; j < 4; j++) {
            int idx = j * 256 + t;
            int r   = idx >> 4;
            int c4  = idx & 15;
            int row = row0 + r;
            float4 v = make_float4(0.f, 0.f, 0.f, 0.f);
            if (row < N_NODES) v = *(const float4*)(in + (size_t)row * 128 + k0 + c4 * 4);
            *(float4*)&xs[r][c4 * 4] = v;
        }
        __syncthreads();
#pragma unroll 8
        for (int kk = 0; kk < 64; kk++) {
            float4 w = *(const float4*)&ws[kk][tx * 4];
#pragma unroll
            for (int i = 0; i < 8; i++) {
                float xv = xs[ty * 8 + i][kk];
                acc[i][0] = fmaf(xv, w.x, acc[i][0]);
                acc[i][1] = fmaf(xv, w.y, acc[i][1]);
                acc[i][2] = fmaf(xv, w.z, acc[i][2]);
                acc[i][3] = fmaf(xv, w.w, acc[i][3]);
            }
        }
        __syncthreads();
    }
#pragma unroll
    for (int i = 0; i < 8; i++) {
        int row = row0 + ty * 8 + i;
        if (row < N_NODES) {
            __nv_bfloat162 p0 = __floats2bfloat162_rn(acc[i][0], acc[i][1]);
            __nv_bfloat162 p1 = __floats2bfloat162_rn(acc[i][2], acc[i][3]);
            uint2 u;
            u.x = *(unsigned int*)&p0;
            u.y = *(unsigned int*)&p1;
            g_hb[(size_t)row * 32 + tx] = u;
        }
    }
}

// ---------------- fused gather + self-loop + bias + ReLU (bf16 h, fp32 accumulate) ----------------
// One warp per dst node; 32 lanes x 4 channels (uint2 bf16x4) cover the 128 channels.
__global__ __launch_bounds__(256) void gather_kernel(const float* __restrict__ b) {
    const int lane = threadIdx.x & 31;
    const int n    = (blockIdx.x * blockDim.x + threadIdx.x) >> 5;
    if (n >= N_NODES) return;

    const float4 bb = *(const float4*)(b + lane * 4);
    float d2 = g_dinv[n];
    d2 = d2 * d2;

    // self-loop term from bf16 h
    uint2 u0 = g_hb[(size_t)n * 32 + lane];
    float2 a0 = __bfloat1622float2(*(__nv_bfloat162*)&u0.x);
    float2 a1 = __bfloat1622float2(*(__nv_bfloat162*)&u0.y);
    float4 acc = make_float4(d2 * a0.x, d2 * a0.y, d2 * a1.x, d2 * a1.y);

    const int beg = g_off[n];
    const int end = g_off[n + 1];

    int e = beg;
    // unroll-2 for memory-level parallelism on the random h gathers
    for (; e + 1 < end; e += 2) {
        int2 e0 = g_edges[e];
        int2 e1 = g_edges[e + 1];
        uint2 v0 = g_hb[(size_t)e0.x * 32 + lane];
        uint2 v1 = g_hb[(size_t)e1.x * 32 + lane];
        float n0 = __int_as_float(e0.y);
        float n1 = __int_as_float(e1.y);
        float2 f00 = __bfloat1622float2(*(__nv_bfloat162*)&v0.x);
        float2 f01 = __bfloat1622float2(*(__nv_bfloat162*)&v0.y);
        float2 f10 = __bfloat1622float2(*(__nv_bfloat162*)&v1.x);
        float2 f11 = __bfloat1622float2(*(__nv_bfloat162*)&v1.y);
        acc.x = fmaf(n0, f00.x, acc.x); acc.y = fmaf(n0, f00.y, acc.y);
        acc.z = fmaf(n0, f01.x, acc.z); acc.w = fmaf(n0, f01.y, acc.w);
        acc.x = fmaf(n1, f10.x, acc.x); acc.y = fmaf(n1, f10.y, acc.y);
        acc.z = fmaf(n1, f11.x, acc.z); acc.w = fmaf(n1, f11.y, acc.w);
    }
    if (e < end) {
        int2 e0 = g_edges[e];
        uint2 v0 = g_hb[(size_t)e0.x * 32 + lane];
        float n0 = __int_as_float(e0.y);
        float2 f00 = __bfloat1622float2(*(__nv_bfloat162*)&v0.x);
        float2 f01 = __bfloat1622float2(*(__nv_bfloat162*)&v0.y);
        acc.x = fmaf(n0, f00.x, acc.x); acc.y = fmaf(n0, f00.y, acc.y);
        acc.z = fmaf(n0, f01.x, acc.z); acc.w = fmaf(n0, f01.y, acc.w);
    }

    float4 o;
    o.x = fmaxf(acc.x + bb.x, 0.f);
    o.y = fmaxf(acc.y + bb.y, 0.f);
    o.z = fmaxf(acc.z + bb.z, 0.f);
    o.w = fmaxf(acc.w + bb.w, 0.f);
    g_x[(size_t)n * 32 + lane] = o;
}

// ---------------- mean pool over graphs (batch is int32) ----------------
__global__ void pool_kernel(const int* __restrict__ batch) {
    const int lane  = threadIdx.x & 31;
    const int warp  = (blockIdx.x * blockDim.x + threadIdx.x) >> 5;
    const int nwarp = (gridDim.x * blockDim.x) >> 5;
    for (int n = warp; n < N_NODES; n += nwarp) {
        int g = batch[n];
        float4 v = g_x[(size_t)n * 32 + lane];
        float4* p = &g_pool[g * 32 + lane];
        asm volatile("red.global.add.v4.f32 [%0], {%1, %2, %3, %4};"
                     :: "l"(p), "f"(v.x), "f"(v.y), "f"(v.z), "f"(v.w)
                     : "memory");
        if (lane == 0) atomicAdd(&g_cnt[g], 1.0f);
    }
}

// ---------------- final: out[g,o] = (pool_sum[g] . Wlin[:,o]) / cnt[g] + blin[o] ----------------
__global__ void final_kernel(const float* __restrict__ Wlin,
                             const float* __restrict__ blin,
                             float* __restrict__ out) {
    __shared__ float ps[128];
    int g = blockIdx.x;
    int o = threadIdx.x;   // 64 threads
    for (int i = o; i < 128; i += 64) ps[i] = ((const float*)g_pool)[g * 128 + i];
    __syncthreads();
    float inv_cnt = 1.0f / fmaxf(g_cnt[g], 1.0f);
    float s = 0.f;
#pragma unroll 8
    for (int k = 0; k < 128; k++) s = fmaf(ps[k], Wlin[k * 64 + o], s);
    out[g * 64 + o] = s * inv_cnt + blin[o];
}

// ---------------- launcher ----------------
extern "C" void kernel_launch(void* const* d_in, const int* in_sizes, int n_in,
                              void* d_out, int out_size) {
    const float* x     = (const float*)d_in[0];
    const int*   ei    = (const int*)d_in[1];     // int32 (JAX x64 disabled)
    const int*   batch = (const int*)d_in[2];     // int32
    const float* W1    = (const float*)d_in[3];
    const float* b1    = (const float*)d_in[4];
    const float* W2    = (const float*)d_in[5];
    const float* b2    = (const float*)d_in[6];
    const float* W3    = (const float*)d_in[7];
    const float* b3    = (const float*)d_in[8];
    const float* Wlin  = (const float*)d_in[9];
    const float* blin  = (const float*)d_in[10];
    float* out = (float*)d_out;

    // Resolve the device address of g_x once (pure query; capture-safe, no alloc).
    static const float* gx_ptr = nullptr;
    if (!gx_ptr) {
        void* p = nullptr;
        cudaGetSymbolAddress(&p, g_x);
        gx_ptr = (const float*)p;
    }

    const int node_blocks   = (N_NODES + 255) / 256;          // 391
    const int gemm_blocks   = (N_NODES + 63) / 64;            // 1563
    const int gather_blocks = (N_NODES * 32 + 255) / 256;     // 12500 (1 warp/node)

    init_misc_kernel<<<node_blocks, 256>>>();
    deg_kernel<<<1024, 256>>>(ei);
    part_kernel<<<SCAN_NB, SCAN_CH>>>();
    scan_part_kernel<<<1, 512>>>();
    offsets_kernel<<<SCAN_NB, SCAN_CH>>>();
    place_kernel<<<1024, 256>>>(ei);

    const float* Ws[3] = { W1, W2, W3 };
    const float* bs[3] = { b1, b2, b3 };

    for (int l = 0; l < 3; l++) {
        const float* in_ptr = (l == 0) ? x : gx_ptr;
        gemm_kernel<<<gemm_blocks, 256>>>(in_ptr, Ws[l]);
        gather_kernel<<<gather_blocks, 256>>>(bs[l]);
    }

    pool_kernel<<<512, 256>>>(batch);
    final_kernel<<<N_GRAPHS, 64>>>(Wlin, blin, out);
}